// round 13
// baseline (speedup 1.0000x reference)
#include <cuda_runtime.h>
#include <cstdint>

#define BB 1024
#define LL 512
#define TT 50
#define TSTART 48
#define TSTOP 49
#define LOG2E 1.4426950408889634f
#define LN2F  0.6931471805599453f
#define RING 16

typedef unsigned long long ull;
typedef long long ll;

__device__ int g_perm[BB];

__device__ __forceinline__ float ex2f(float x){
    float r; asm("ex2.approx.ftz.f32 %0, %1;" : "=f"(r) : "f"(x)); return r;
}
__device__ __forceinline__ ull pack2(float x, float y){
    ull r; asm("mov.b64 %0, {%1,%2};" : "=l"(r) : "f"(x), "f"(y)); return r;
}
__device__ __forceinline__ void unpack2(ull v, float &x, float &y){
    asm("mov.b64 {%0,%1}, %2;" : "=f"(x), "=f"(y) : "l"(v));
}
__device__ __forceinline__ void ffma2(ull &d, ull a, ull b){
    asm("fma.rn.f32x2 %0, %1, %2, %0;" : "+l"(d) : "l"(a), "l"(b));
}
__device__ __forceinline__ ull add2(ull a, ull b){
    ull r; asm("add.rn.f32x2 %0, %1, %2;" : "=l"(r) : "l"(a), "l"(b)); return r;
}
__device__ __forceinline__ uint32_t redux_max_bits(float x){
    uint32_t r; asm("redux.sync.max.u32 %0, %1, 0xffffffff;" : "=r"(r) : "r"(__float_as_uint(x))); return r;
}
__device__ __forceinline__ uint32_t saddr(const void* p){
    return (uint32_t)__cvta_generic_to_shared(p);
}
__device__ __forceinline__ void cp8(uint32_t dst, const float* src){
    asm volatile("cp.async.ca.shared.global [%0], [%1], 8;" :: "r"(dst), "l"(src));
}
__device__ __forceinline__ void cp_commit(){ asm volatile("cp.async.commit_group;"); }
__device__ __forceinline__ void cp_wait0(){ asm volatile("cp.async.wait_group 0;"); }
__device__ __forceinline__ void cp_wait1(){ asm volatile("cp.async.wait_group 1;"); }
__device__ __forceinline__ void cp_wait2(){ asm volatile("cp.async.wait_group 2;"); }

// 50x50 mat-vec: 52 packed FMAs from 13 LDS.128, 8 shallow accumulator chains
__device__ __forceinline__ void matvec50(const float* wb, const ull* E0, const ull* E1,
                                         float &s0, float &s1){
    const ulonglong2* vb2 = (const ulonglong2*)wb;
    ull A0[8] = {0,0,0,0,0,0,0,0}, A1[8] = {0,0,0,0,0,0,0,0};
#pragma unroll
    for (int q = 0; q < 13; q++){
        ulonglong2 z = vb2[q];
        ffma2(A0[(2*q)&7], E0[2*q], z.x);     ffma2(A1[(2*q)&7], E1[2*q], z.x);
        ffma2(A0[(2*q+1)&7], E0[2*q+1], z.y); ffma2(A1[(2*q+1)&7], E1[2*q+1], z.y);
    }
    ull t0 = add2(add2(add2(A0[0],A0[1]), add2(A0[2],A0[3])),
                  add2(add2(A0[4],A0[5]), add2(A0[6],A0[7])));
    ull t1 = add2(add2(add2(A1[0],A1[1]), add2(A1[2],A1[3])),
                  add2(add2(A1[4],A1[5]), add2(A1[6],A1[7])));
    float x, y;
    unpack2(t0,x,y); s0 = x + y;
    unpack2(t1,x,y); s1 = x + y;
}

// Longest-first schedule (counting sort by len desc) + output zeroing.
__global__ void __launch_bounds__(512) sched(const int* __restrict__ lens, float* __restrict__ out){
    __shared__ int hist[512];
    __shared__ int base[512];
    const int tid = threadIdx.x;
    if (tid == 0) out[0] = 0.f;
    hist[tid] = 0;
    __syncthreads();
    for (int i = tid; i < BB; i += 512)
        atomicAdd(&hist[LL - __ldg(&lens[i])], 1);
    __syncthreads();
    int cnt = hist[tid];
    for (int o = 1; o < 512; o <<= 1){
        int v = (tid >= o) ? hist[tid - o] : 0;
        __syncthreads();
        hist[tid] += v;
        __syncthreads();
    }
    base[tid] = hist[tid] - cnt;
    __syncthreads();
    for (int i = tid; i < BB; i += 512){
        int bin = LL - __ldg(&lens[i]);
        g_perm[atomicAdd(&base[bin], 1)] = i;
    }
}

#define GRID 296
#define R2B  216   // blocks that take a second (folded short) pair

__global__ void __launch_bounds__(128)
crf_fwd(const float* __restrict__ logits,
        const float* __restrict__ trans,
        const int*   __restrict__ labels,
        const int*   __restrict__ lens,
        float* __restrict__ out)
{
    __shared__ float ring[4][RING][64];  // per-warp 16-deep logits-row ring
    __shared__ float vbuf[4][2][64];     // per-warp double-buffered vector broadcast
    __shared__ float xsh[2][64];         // fwd warp's final vector, per pair
    __shared__ float offsh[2];

    const int warp  = threadIdx.x >> 5;
    const int lane  = threadIdx.x & 31;
    const int pairI = warp >> 1;
    const int dir   = warp & 1;                 // 0 fwd, 1 bwd
    const int bid   = blockIdx.x;

    const int j0 = lane;
    const int j1 = lane + 32;
    const bool hasJ1 = (j1 < TT);

    // vbuf tails (slots >= 50) must stay 0 forever
    vbuf[warp][0][lane] = 0.f; vbuf[warp][0][lane+32] = 0.f;
    vbuf[warp][1][lane] = 0.f; vbuf[warp][1][lane+32] = 0.f;

    // E rows (fwd: E, bwd: E^T) — constant across both pairs; load once
    ull E0[26], E1[26];
#pragma unroll
    for (int p = 0; p < 25; p++){
        int k0 = 2*p, k1 = 2*p + 1;
        float e00, e01, e10 = 0.f, e11 = 0.f;
        if (!dir){
            e00 = __ldg(&trans[j0*TT + k0]); e01 = __ldg(&trans[j0*TT + k1]);
            if (hasJ1){ e10 = __ldg(&trans[j1*TT + k0]); e11 = __ldg(&trans[j1*TT + k1]); }
        } else {
            e00 = __ldg(&trans[k0*TT + j0]); e01 = __ldg(&trans[k1*TT + j0]);
            if (hasJ1){ e10 = __ldg(&trans[k0*TT + j1]); e11 = __ldg(&trans[k1*TT + j1]); }
        }
        E0[p] = pack2(ex2f(LOG2E*e00), ex2f(LOG2E*e01));
        E1[p] = hasJ1 ? pack2(ex2f(LOG2E*e10), ex2f(LOG2E*e11)) : 0ull;
    }
    E0[25] = 0ull; E1[25] = 0ull;

    for (int r = 0; r < 2; r++){
        if (r == 1 && bid >= R2B) break;
        const int slotIdx = (r == 0) ? (bid * 2 + pairI)
                                     : (2*GRID + 2 * (R2B - 1 - bid) + pairI);
        const int b = g_perm[slotIdx];

        const int len = __ldg(&lens[b]);
        const int h   = len >> 1;
        const int steps = dir ? (len - h - 1) : h;
        const int maxq  = dir ? (len - 1 - h) : max(h - 1, 0);
        const float* __restrict__ rowp   = logits + (ll)b * LL * TT;
        const int*   __restrict__ labrow = labels + (ll)b * LL;

        // ---- prologue: 3 groups of 4 rows (slots 0..11), clamped
#pragma unroll
        for (int g = 0; g < 3; g++){
            if (lane < 25){
#pragma unroll
                for (int k = 0; k < 4; k++){
                    int q = 4*g + k;
                    int m = min(q, maxq);
                    int trow = dir ? (len - 1 - m) : m;
                    cp8(saddr(&ring[warp][q][0]) + lane*8u, rowp + (ll)trow*TT + lane*2);
                }
            }
            cp_commit();
        }

        // ---- score phase (lane-parallel; overlaps prologue DRAM latency)
        float em = 0.f, tr = 0.f;
        {
            int ta = dir ? h : 0;
            int tb = dir ? len : h;
            for (int t = ta + lane; t < tb; t += 32){
                int lab = __ldg(&labrow[t]);
                int prv = (t == 0) ? TSTART : __ldg(&labrow[t - 1]);
                em += __ldg(&rowp[(ll)t*TT + lab]);
                tr += __ldg(&trans[lab*TT + prv]);
            }
            if (dir && lane == 0)
                tr += __ldg(&trans[TSTOP*TT + __ldg(&labrow[len - 1])]);
        }

        // ---- state init
        float mlo, mhi;
        int off = 0;
        if (!dir){
            mlo = 0.f; mhi = (j1 == TSTART) ? 1.f : 0.f;
        } else {
            float u0 = ex2f(LOG2E * __ldg(&trans[TSTOP*TT + j0]));
            float u1 = hasJ1 ? ex2f(LOG2E * __ldg(&trans[TSTOP*TT + j1])) : 0.f;
            cp_wait2(); __syncwarp();           // group 0 (slots 0..3) complete
            mlo = u0 * ex2f(LOG2E * ring[warp][0][j0]);
            mhi = hasJ1 ? (u1 * ex2f(LOG2E * ring[warp][0][j1])) : 0.f;
        }

#define STEP_NP(I, PH) { \
        float* wb = &vbuf[warp][PH][0]; \
        wb[j0] = mlo; \
        if (hasJ1) wb[j1] = mhi; \
        __syncwarp(); \
        const float* srow = &ring[warp][((I) + dir) & (RING-1)][0]; \
        float p0 = ex2f(LOG2E * srow[j0]); \
        float p1 = hasJ1 ? ex2f(LOG2E * srow[j1]) : 0.f; \
        float s0, s1; \
        matvec50(wb, E0, E1, s0, s1); \
        mlo = p0 * s0; \
        mhi = hasJ1 ? (p1 * s1) : 0.f; }

#define RENORM { \
        uint32_t mb = redux_max_bits(fmaxf(mlo, mhi)); \
        int k = max((int)(mb >> 23) - 127, -126); \
        off += k; \
        float scn = __int_as_float((127 - k) << 23); \
        mlo *= scn; mhi *= scn; }

        // ---- main loop: chunks of 4 steps, one prefetch group (4 rows) per chunk,
        // unclamped pointer-stepped rows (in-bounds proven for steps >= 12)
        const int M = (steps >= 12) ? ((steps - 8) & ~3) : 0;
        const ll qstep = dir ? -(ll)TT : (ll)TT;
        const float* pf = dir ? (rowp + (ll)(len - 13) * TT) : (rowp + 12 * TT);

        int i = 0;
        for (; i < M; i += 4){
            cp_wait1();                         // groups <= chunk+1 complete -> slots <= i+7
            if (lane < 25){
                uint32_t d0 = saddr(&ring[warp][(i+12) & (RING-1)][0]) + lane*8u;
                cp8(d0,                 pf            + lane*2);
                cp8(d0 + 256u,          pf +   qstep  + lane*2);   // slots are contiguous mod RING
                cp8(saddr(&ring[warp][(i+14) & (RING-1)][0]) + lane*8u, pf + 2*qstep + lane*2);
                cp8(saddr(&ring[warp][(i+15) & (RING-1)][0]) + lane*8u, pf + 3*qstep + lane*2);
            }
            cp_commit();
            pf += 4 * qstep;
            STEP_NP(i,   0); STEP_NP(i+1, 1); STEP_NP(i+2, 0); STEP_NP(i+3, 1);
            RENORM;
        }
        cp_wait0();                             // everything landed; tail is pure compute
        for (; i < steps; i++){
            STEP_NP(i, (i & 1));
            if ((i & 3) == 3) RENORM;
        }

        if (dir){   // bwd epilogue: bare y = E^T z
            float* wb = &vbuf[warp][steps & 1][0];
            wb[j0] = mlo;
            if (hasJ1) wb[j1] = mhi;
            __syncwarp();
            float s0, s1;
            matvec50(wb, E0, E1, s0, s1);
            mlo = s0; mhi = s1;
        } else {    // fwd publishes final vector + offset
            xsh[pairI][j0] = mlo;
            if (hasJ1) xsh[pairI][j1] = mhi;
            if (lane == 0) offsh[pairI] = (float)off;
        }
        asm volatile("bar.sync %0, %1;" :: "r"(1 + pairI), "r"(64) : "memory");

        float sc = em + tr;
#pragma unroll
        for (int o = 16; o; o >>= 1) sc += __shfl_xor_sync(0xffffffffu, sc, o);

        if (!dir){
            if (lane == 0) atomicAdd(out, -sc * (1.0f / BB));
        } else {
            float d = mlo * xsh[pairI][j0] + (hasJ1 ? mhi * xsh[pairI][j1] : 0.f);
#pragma unroll
            for (int o = 16; o; o >>= 1) d += __shfl_xor_sync(0xffffffffu, d, o);
            if (lane == 0){
                float part = LN2F * ((float)off + offsh[pairI] + log2f(d));
                atomicAdd(out, (part - sc) * (1.0f / BB));
            }
        }
        // protect xsh/offsh reuse by the next pair
        asm volatile("bar.sync %0, %1;" :: "r"(1 + pairI), "r"(64) : "memory");
#undef STEP_NP
#undef RENORM
    }
}

extern "C" void kernel_launch(void* const* d_in, const int* in_sizes, int n_in,
                              void* d_out, int out_size)
{
    const float* logits = (const float*)d_in[0];
    const float* trans  = (const float*)d_in[1];
    const int*   labels = (const int*)d_in[2];
    const int*   lens   = (const int*)d_in[3];
    float* out = (float*)d_out;
    sched<<<1, 512>>>(lens, out);
    crf_fwd<<<GRID, 128>>>(logits, trans, labels, lens, out);
}